// round 4
// baseline (speedup 1.0000x reference)
#include <cuda_runtime.h>
#include <cstdint>

#define DIM      128
#define BM       128
#define THREADS  512
#define SROW     130                 // InT row stride in floats (8B aligned, 8-way-max conflicts)
#define N_MAX    100000

// scratch for segment_sum (no cudaMalloc allowed)
__device__ float g_agg[(size_t)N_MAX * DIM];
__device__ int   g_idx64;            // 1 if edge_index buffer is int64, 0 if int32

static const int SMEM_FLOATS = 256 * SROW + 64 * 256;   // InT + duplicated weight chunk
static const int SMEM_BYTES  = SMEM_FLOATS * 4;         // 198656 B

// packed f32x2 FMA: c(pair) += a(pair) * b(pair)
#define FMA2(c, a, b) asm("fma.rn.f32x2 %0, %1, %2, %0;" : "+l"(c) : "l"(a), "l"(b))

__device__ __forceinline__ float mish_f(float v) {
    // mish(v) = v * tanh(softplus(v)) = v * t(t+2) / (t(t+2)+2), t = e^v  (clip to avoid overflow)
    float t = __expf(fminf(v, 40.0f));
    float num = t * (t + 2.0f);
    return v * (num / (num + 2.0f));
}

// One 64-row K-chunk GEMM stage, accumulating C[128][128] across the block.
// A: transposed input tile InT[k][SROW] in smem. W: [K][128] row-major global, staged
// into smem duplicated per element so B pairs load directly as 64-bit (no packing).
__device__ __forceinline__ void gemm_stage(
    const float* __restrict__ A, float* __restrict__ WSd,
    const float* __restrict__ W, int K,
    int tm, int tn, int tid, unsigned long long acc[4][4])
{
    for (int kb = 0; kb < K; kb += 64) {
        __syncthreads();
        {
            const float2* Wg = (const float2*)W + (size_t)kb * 64;  // kb rows * 64 float2/row
            float4* WSd4 = (float4*)WSd;
#pragma unroll
            for (int t = 0; t < 8; t++) {          // 64*64 float2 / 512 threads
                int idx = tid + t * THREADS;
                float2 w = Wg[idx];
                WSd4[idx] = make_float4(w.x, w.x, w.y, w.y);
            }
        }
        __syncthreads();
#pragma unroll 8
        for (int kk = 0; kk < 64; kk++) {
            const unsigned long long* ar =
                (const unsigned long long*)(A + (size_t)(kb + kk) * SROW) + tm * 4;
            unsigned long long am0 = ar[0];
            unsigned long long am1 = ar[1];
            unsigned long long am2 = ar[2];
            unsigned long long am3 = ar[3];
            const ulonglong2* br = (const ulonglong2*)(WSd + kk * 256 + tn * 8);
            ulonglong2 b01 = br[0];
            ulonglong2 b23 = br[1];
            FMA2(acc[0][0], am0, b01.x); FMA2(acc[0][1], am0, b01.y);
            FMA2(acc[0][2], am0, b23.x); FMA2(acc[0][3], am0, b23.y);
            FMA2(acc[1][0], am1, b01.x); FMA2(acc[1][1], am1, b01.y);
            FMA2(acc[1][2], am1, b23.x); FMA2(acc[1][3], am1, b23.y);
            FMA2(acc[2][0], am2, b01.x); FMA2(acc[2][1], am2, b01.y);
            FMA2(acc[2][2], am2, b23.x); FMA2(acc[2][3], am2, b23.y);
            FMA2(acc[3][0], am3, b01.x); FMA2(acc[3][1], am3, b01.y);
            FMA2(acc[3][2], am3, b23.x); FMA2(acc[3][3], am3, b23.y);
        }
    }
}

// In-tile 2-layer MLP: H = mish(InT^T @ W1 + b1); Out = H @ W2 + b2.
// InT rows [0..255] hold the K=256 input (transposed). H is written back
// transposed into InT rows [0..127] and used as A for the second GEMM.
__device__ __forceinline__ void mlp_tile(
    float* __restrict__ InT, float* __restrict__ WSd,
    const float* __restrict__ W1, const float* __restrict__ b1,
    const float* __restrict__ W2, const float* __restrict__ b2,
    float* __restrict__ out, int r0, int nvalid)
{
    const int tid = threadIdx.x;
    const int tm = tid & 15;     // 16 groups of 8 rows
    const int tn = tid >> 4;     // 32 groups of 4 cols

    unsigned long long acc[4][4];
#pragma unroll
    for (int i = 0; i < 4; i++)
#pragma unroll
        for (int j = 0; j < 4; j++) acc[i][j] = 0ULL;

    gemm_stage(InT, WSd, W1, 2 * DIM, tm, tn, tid, acc);
    __syncthreads();   // everyone done reading InT before H overwrites rows [0..127]

    {
        float bb[4];
#pragma unroll
        for (int c = 0; c < 4; c++) bb[c] = b1[tn * 4 + c];
#pragma unroll
        for (int mp = 0; mp < 4; mp++) {
#pragma unroll
            for (int c = 0; c < 4; c++) {
                float2 v = *(float2*)&acc[mp][c];
                v.x = mish_f(v.x + bb[c]);
                v.y = mish_f(v.y + bb[c]);
                *(float2*)(InT + (size_t)(tn * 4 + c) * SROW + tm * 8 + 2 * mp) = v;
            }
        }
    }

#pragma unroll
    for (int i = 0; i < 4; i++)
#pragma unroll
        for (int j = 0; j < 4; j++) acc[i][j] = 0ULL;

    // gemm_stage's leading __syncthreads orders H writes before H reads
    gemm_stage(InT, WSd, W2, DIM, tm, tn, tid, acc);

    {
        float cb[4];
#pragma unroll
        for (int c = 0; c < 4; c++) cb[c] = b2[tn * 4 + c];
        float4* out4 = (float4*)out;
#pragma unroll
        for (int mp = 0; mp < 4; mp++) {
            int row0 = tm * 8 + 2 * mp;
            float2 v0 = *(float2*)&acc[mp][0];
            float2 v1 = *(float2*)&acc[mp][1];
            float2 v2 = *(float2*)&acc[mp][2];
            float2 v3 = *(float2*)&acc[mp][3];
            float4 lo = make_float4(v0.x + cb[0], v1.x + cb[1], v2.x + cb[2], v3.x + cb[3]);
            float4 hi = make_float4(v0.y + cb[0], v1.y + cb[1], v2.y + cb[2], v3.y + cb[3]);
            if (row0 < nvalid)     out4[(size_t)(r0 + row0) * 32 + tn] = lo;
            if (row0 + 1 < nvalid) out4[(size_t)(r0 + row0 + 1) * 32 + tn] = hi;
        }
    }
}

__global__ void __launch_bounds__(THREADS, 1) zero_agg_kernel(int n4) {
    int i = blockIdx.x * blockDim.x + threadIdx.x;
    if (i < n4) ((float4*)g_agg)[i] = make_float4(0.f, 0.f, 0.f, 0.f);
}

// Detect edge_index dtype: little-endian int64 indices (< 2^31) have all-zero
// odd 32-bit words; int32 layout has src[1],src[3],... there (never all zero).
__global__ void detect_idx_kernel(const int* __restrict__ eidx) {
    __shared__ int any;
    if (threadIdx.x == 0) any = 0;
    __syncthreads();
    for (int k = threadIdx.x; k < 1024; k += blockDim.x) {
        if (eidx[2 * k + 1] != 0) any = 1;   // benign race, write-only of same value
    }
    __syncthreads();
    if (threadIdx.x == 0) g_idx64 = (any == 0) ? 1 : 0;
}

__global__ void __launch_bounds__(THREADS, 1) edge_kernel(
    const float* __restrict__ x, const float* __restrict__ ea,
    const int* __restrict__ eidx,
    const float* __restrict__ W1, const float* __restrict__ b1,
    const float* __restrict__ W2, const float* __restrict__ b2,
    float* __restrict__ eout, int E)
{
    extern __shared__ float sm[];
    float* InT = sm;                 // [256][SROW] transposed input tile
    float* WSd = sm + 256 * SROW;    // [64][256] duplicated weight chunk
    __shared__ int ssrc[BM];
    __shared__ int sdst[BM];

    const int tid = threadIdx.x;
    const int r0 = blockIdx.x * BM;
    const int nvalid = min(BM, E - r0);

    if (tid < BM) {
        int s = 0, d = 0;
        if (tid < nvalid) {
            if (g_idx64) {
                const long long* e64 = (const long long*)eidx;
                s = (int)e64[r0 + tid];
                d = (int)e64[(size_t)E + r0 + tid];
            } else {
                s = eidx[r0 + tid];
                d = eidx[E + r0 + tid];
            }
        }
        ssrc[tid] = s;
        sdst[tid] = d;
    }
    __syncthreads();

    const float4* ea4 = (const float4*)ea;
    const float4* x4 = (const float4*)x;
#pragma unroll
    for (int t = 0; t < (BM * 32) / THREADS; t++) {
        int idx = tid + t * THREADS;
        int i = idx >> 5, c4 = idx & 31;
        int k = c4 * 4;
        float4 v = make_float4(0.f, 0.f, 0.f, 0.f);
        float4 g = make_float4(0.f, 0.f, 0.f, 0.f);
        if (i < nvalid) {
            v = ea4[(size_t)(r0 + i) * 32 + c4];
            int s = ssrc[i], d = sdst[i];
            float4 a = x4[(size_t)s * 32 + c4];
            float4 b = x4[(size_t)d * 32 + c4];
            g = make_float4(a.x + b.x, a.y + b.y, a.z + b.z, a.w + b.w);
            float* ag = g_agg + (size_t)d * DIM + k;     // segment_sum of edge_attr over dst
            atomicAdd(ag + 0, v.x);
            atomicAdd(ag + 1, v.y);
            atomicAdd(ag + 2, v.z);
            atomicAdd(ag + 3, v.w);
        }
        InT[(size_t)(k + 0) * SROW + i] = v.x;
        InT[(size_t)(k + 1) * SROW + i] = v.y;
        InT[(size_t)(k + 2) * SROW + i] = v.z;
        InT[(size_t)(k + 3) * SROW + i] = v.w;
        InT[(size_t)(128 + k + 0) * SROW + i] = g.x;
        InT[(size_t)(128 + k + 1) * SROW + i] = g.y;
        InT[(size_t)(128 + k + 2) * SROW + i] = g.z;
        InT[(size_t)(128 + k + 3) * SROW + i] = g.w;
    }
    __syncthreads();

    mlp_tile(InT, WSd, W1, b1, W2, b2, eout, r0, nvalid);
}

__global__ void __launch_bounds__(THREADS, 1) node_kernel(
    const float* __restrict__ x,
    const float* __restrict__ W1, const float* __restrict__ b1,
    const float* __restrict__ W2, const float* __restrict__ b2,
    float* __restrict__ xout, int N)
{
    extern __shared__ float sm[];
    float* InT = sm;
    float* WSd = sm + 256 * SROW;

    const int tid = threadIdx.x;
    const int r0 = blockIdx.x * BM;
    const int nvalid = min(BM, N - r0);

    const float4* x4 = (const float4*)x;
    const float4* ag4 = (const float4*)g_agg;
#pragma unroll
    for (int t = 0; t < (BM * 32) / THREADS; t++) {
        int idx = tid + t * THREADS;
        int i = idx >> 5, c4 = idx & 31;
        int k = c4 * 4;
        float4 v = make_float4(0.f, 0.f, 0.f, 0.f);
        float4 g = make_float4(0.f, 0.f, 0.f, 0.f);
        if (i < nvalid) {
            v = x4[(size_t)(r0 + i) * 32 + c4];
            g = ag4[(size_t)(r0 + i) * 32 + c4];
        }
        InT[(size_t)(k + 0) * SROW + i] = v.x;
        InT[(size_t)(k + 1) * SROW + i] = v.y;
        InT[(size_t)(k + 2) * SROW + i] = v.z;
        InT[(size_t)(k + 3) * SROW + i] = v.w;
        InT[(size_t)(128 + k + 0) * SROW + i] = g.x;
        InT[(size_t)(128 + k + 1) * SROW + i] = g.y;
        InT[(size_t)(128 + k + 2) * SROW + i] = g.z;
        InT[(size_t)(128 + k + 3) * SROW + i] = g.w;
    }
    __syncthreads();

    mlp_tile(InT, WSd, W1, b1, W2, b2, xout, r0, nvalid);
}

extern "C" void kernel_launch(void* const* d_in, const int* in_sizes, int n_in,
                              void* d_out, int out_size)
{
    const float* x    = (const float*)d_in[0];
    const float* ea   = (const float*)d_in[1];
    const int*   eidx = (const int*)d_in[2];
    const float* eW1  = (const float*)d_in[3];
    const float* eb1  = (const float*)d_in[4];
    const float* eW2  = (const float*)d_in[5];
    const float* eb2  = (const float*)d_in[6];
    const float* nW1  = (const float*)d_in[7];
    const float* nb1  = (const float*)d_in[8];
    const float* nW2  = (const float*)d_in[9];
    const float* nb2  = (const float*)d_in[10];
    float* out = (float*)d_out;

    const int N = in_sizes[0] / DIM;
    const int E = in_sizes[1] / DIM;

    cudaFuncSetAttribute(edge_kernel, cudaFuncAttributeMaxDynamicSharedMemorySize, SMEM_BYTES);
    cudaFuncSetAttribute(node_kernel, cudaFuncAttributeMaxDynamicSharedMemorySize, SMEM_BYTES);

    // 0) detect edge_index dtype (int32 vs int64)
    detect_idx_kernel<<<1, 256>>>(eidx);

    // 1) zero the aggregation scratch
    int n4 = N * (DIM / 4);
    zero_agg_kernel<<<(n4 + THREADS - 1) / THREADS, THREADS>>>(n4);

    // 2) edge MLP (writes e) + scatter-sum of edge_attr into g_agg
    float* e_out = out + (size_t)N * DIM;   // output tuple order: (x_out, e)
    edge_kernel<<<(E + BM - 1) / BM, THREADS, SMEM_BYTES>>>(
        x, ea, eidx, eW1, eb1, eW2, eb2, e_out, E);

    // 3) node MLP on [x, agg] (stream order guarantees agg is complete)
    node_kernel<<<(N + BM - 1) / BM, THREADS, SMEM_BYTES>>>(
        x, nW1, nb1, nW2, nb2, out, N);
}

// round 5
// speedup vs baseline: 1.8301x; 1.8301x over previous
#include <cuda_runtime.h>
#include <cstdint>

#define DIM      128
#define BM       128
#define THREADS  512
#define SROW     130                 // InT row stride in floats (row bases 8B aligned)
#define N_MAX    100000

// scratch for segment_sum (no cudaMalloc allowed)
__device__ float g_agg[(size_t)N_MAX * DIM];
__device__ int   g_idx64;            // 1 if edge_index buffer is int64, 0 if int32

static const int SMEM_FLOATS = 256 * SROW + 64 * DIM;   // InT + weight chunk (no duplication)
static const int SMEM_BYTES  = SMEM_FLOATS * 4;         // 165888 B

// packed f32x2 FMA: c(pair) += a(pair) * b(pair)
#define FMA2(c, a, b) asm("fma.rn.f32x2 %0, %1, %2, %0;" : "+l"(c) : "l"(a), "l"(b))
// duplicate a float into both halves of a 64-bit packed pair
#define DUP2(d, f) do { unsigned _u = __float_as_uint(f); \
    asm("mov.b64 %0, {%1, %1};" : "=l"(d) : "r"(_u)); } while (0)

__device__ __forceinline__ float mish_f(float v) {
    // mish(v) = v * tanh(softplus(v)) = v * t(t+2) / (t(t+2)+2), t = e^v
    float t = __expf(fminf(v, 40.0f));
    float num = t * (t + 2.0f);
    return v * (num / (num + 2.0f));
}

// One GEMM: C[128][128] += A(InT, transposed, rows=k)[K][128] ^T-logical @ W[K][128].
// Accumulators paired along N. Conflict-free LDS patterns (see mapping in mlp_tile).
__device__ __forceinline__ void gemm_stage(
    const float* __restrict__ A, float* __restrict__ WS,
    const float* __restrict__ W, int K,
    int mg, int ng, int tid, unsigned long long acc[8][2])
{
    for (int kb = 0; kb < K; kb += 64) {
        __syncthreads();
        {
            const float4* Wg = (const float4*)(W + (size_t)kb * DIM);
            float4* WS4 = (float4*)WS;
#pragma unroll
            for (int t = 0; t < 4; t++) {          // 64*128 floats / (512 thr * 4)
                int idx = tid + t * THREADS;
                WS4[idx] = Wg[idx];
            }
        }
        __syncthreads();
#pragma unroll 4
        for (int kk = 0; kk < 64; kk++) {
            const float* ar = A + (size_t)(kb + kk) * SROW + mg * 8;
            float2 a0 = *(const float2*)(ar + 0);
            float2 a1 = *(const float2*)(ar + 2);
            float2 a2 = *(const float2*)(ar + 4);
            float2 a3 = *(const float2*)(ar + 6);
            ulonglong2 bv = *(const ulonglong2*)(WS + kk * DIM + ng * 4);
            unsigned long long d0, d1, d2, d3, d4, d5, d6, d7;
            DUP2(d0, a0.x); DUP2(d1, a0.y);
            DUP2(d2, a1.x); DUP2(d3, a1.y);
            DUP2(d4, a2.x); DUP2(d5, a2.y);
            DUP2(d6, a3.x); DUP2(d7, a3.y);
            FMA2(acc[0][0], d0, bv.x); FMA2(acc[0][1], d0, bv.y);
            FMA2(acc[1][0], d1, bv.x); FMA2(acc[1][1], d1, bv.y);
            FMA2(acc[2][0], d2, bv.x); FMA2(acc[2][1], d2, bv.y);
            FMA2(acc[3][0], d3, bv.x); FMA2(acc[3][1], d3, bv.y);
            FMA2(acc[4][0], d4, bv.x); FMA2(acc[4][1], d4, bv.y);
            FMA2(acc[5][0], d5, bv.x); FMA2(acc[5][1], d5, bv.y);
            FMA2(acc[6][0], d6, bv.x); FMA2(acc[6][1], d6, bv.y);
            FMA2(acc[7][0], d7, bv.x); FMA2(acc[7][1], d7, bv.y);
        }
    }
}

// In-tile 2-layer MLP: H = mish(In @ W1 + b1); Out = H @ W2 + b2.
// InT rows [0..K1) hold the input transposed (row = feature, col = sample).
// H is written back transposed into InT rows [0..127] and used for GEMM2.
__device__ __forceinline__ void mlp_tile(
    float* __restrict__ InT, float* __restrict__ WS,
    const float* __restrict__ W1, const float* __restrict__ b1,
    const float* __restrict__ W2, const float* __restrict__ b2,
    float* __restrict__ out, int r0, int nvalid)
{
    const int tid  = threadIdx.x;
    const int warp = tid >> 5;
    const int lane = tid & 31;
    const int mg = (warp & 3) * 4 + (lane >> 3);   // 0..15 : rows mg*8 .. mg*8+7
    const int ng = (warp >> 2) * 8 + (lane & 7);   // 0..31 : cols ng*4 .. ng*4+3

    unsigned long long acc[8][2];
#pragma unroll
    for (int i = 0; i < 8; i++) { acc[i][0] = 0ULL; acc[i][1] = 0ULL; }

    gemm_stage(InT, WS, W1, 2 * DIM, mg, ng, tid, acc);
    __syncthreads();   // all reads of InT done before H overwrites rows [0..127]

    {
        float4 bb = *(const float4*)(b1 + ng * 4);
#pragma unroll
        for (int mp = 0; mp < 8; mp++) {
            int m = mg * 8 + mp;
            float2 v0 = *(float2*)&acc[mp][0];
            float2 v1 = *(float2*)&acc[mp][1];
            v0.x = mish_f(v0.x + bb.x);
            v0.y = mish_f(v0.y + bb.y);
            v1.x = mish_f(v1.x + bb.z);
            v1.y = mish_f(v1.y + bb.w);
            InT[(size_t)(ng * 4 + 0) * SROW + m] = v0.x;
            InT[(size_t)(ng * 4 + 1) * SROW + m] = v0.y;
            InT[(size_t)(ng * 4 + 2) * SROW + m] = v1.x;
            InT[(size_t)(ng * 4 + 3) * SROW + m] = v1.y;
        }
    }

#pragma unroll
    for (int i = 0; i < 8; i++) { acc[i][0] = 0ULL; acc[i][1] = 0ULL; }

    // gemm_stage's leading __syncthreads orders H writes before H reads
    gemm_stage(InT, WS, W2, DIM, mg, ng, tid, acc);

    {
        float4 cb = *(const float4*)(b2 + ng * 4);
        float4* out4 = (float4*)out;
#pragma unroll
        for (int mp = 0; mp < 8; mp++) {
            int m = mg * 8 + mp;
            if (m < nvalid) {
                float2 v0 = *(float2*)&acc[mp][0];
                float2 v1 = *(float2*)&acc[mp][1];
                float4 o = make_float4(v0.x + cb.x, v0.y + cb.y,
                                       v1.x + cb.z, v1.y + cb.w);
                out4[(size_t)(r0 + m) * 32 + ng] = o;
            }
        }
    }
}

__global__ void __launch_bounds__(THREADS, 1) zero_agg_kernel(int n4) {
    int i = blockIdx.x * blockDim.x + threadIdx.x;
    if (i < n4) ((float4*)g_agg)[i] = make_float4(0.f, 0.f, 0.f, 0.f);
}

// Detect edge_index dtype: little-endian int64 indices (< 2^31) have all-zero
// odd 32-bit words; int32 layout has src[1],src[3],... there (never all zero).
__global__ void detect_idx_kernel(const int* __restrict__ eidx) {
    __shared__ int any;
    if (threadIdx.x == 0) any = 0;
    __syncthreads();
    for (int k = threadIdx.x; k < 1024; k += blockDim.x) {
        if (eidx[2 * k + 1] != 0) any = 1;   // benign race, same value
    }
    __syncthreads();
    if (threadIdx.x == 0) g_idx64 = (any == 0) ? 1 : 0;
}

__global__ void __launch_bounds__(THREADS, 1) edge_kernel(
    const float* __restrict__ x, const float* __restrict__ ea,
    const int* __restrict__ eidx,
    const float* __restrict__ W1, const float* __restrict__ b1,
    const float* __restrict__ W2, const float* __restrict__ b2,
    float* __restrict__ eout, int E)
{
    extern __shared__ float sm[];
    float* InT = sm;                 // [256][SROW] transposed input tile
    float* WS  = sm + 256 * SROW;    // [64][128] weight chunk
    __shared__ int ssrc[BM];
    __shared__ int sdst[BM];

    const int tid = threadIdx.x;
    const int r0 = blockIdx.x * BM;
    const int nvalid = min(BM, E - r0);

    if (tid < BM) {
        int s = 0, d = 0;
        if (tid < nvalid) {
            if (g_idx64) {
                const long long* e64 = (const long long*)eidx;
                s = (int)e64[r0 + tid];
                d = (int)e64[(size_t)E + r0 + tid];
            } else {
                s = eidx[r0 + tid];
                d = eidx[E + r0 + tid];
            }
        }
        ssrc[tid] = s;
        sdst[tid] = d;
    }
    __syncthreads();

    const float4* ea4 = (const float4*)ea;
    const float4* x4 = (const float4*)x;
#pragma unroll
    for (int t = 0; t < (BM * 32) / THREADS; t++) {
        int idx = tid + t * THREADS;
        int i = idx >> 5, c4 = idx & 31;
        int k = c4 * 4;
        float4 v = make_float4(0.f, 0.f, 0.f, 0.f);
        float4 g = make_float4(0.f, 0.f, 0.f, 0.f);
        if (i < nvalid) {
            v = ea4[(size_t)(r0 + i) * 32 + c4];
            int s = ssrc[i], d = sdst[i];
            float4 a = x4[(size_t)s * 32 + c4];
            float4 b = x4[(size_t)d * 32 + c4];
            g = make_float4(a.x + b.x, a.y + b.y, a.z + b.z, a.w + b.w);
            float* ag = g_agg + (size_t)d * DIM + k;     // segment_sum of edge_attr over dst
            atomicAdd(ag + 0, v.x);
            atomicAdd(ag + 1, v.y);
            atomicAdd(ag + 2, v.z);
            atomicAdd(ag + 3, v.w);
        }
        InT[(size_t)(k + 0) * SROW + i] = v.x;
        InT[(size_t)(k + 1) * SROW + i] = v.y;
        InT[(size_t)(k + 2) * SROW + i] = v.z;
        InT[(size_t)(k + 3) * SROW + i] = v.w;
        InT[(size_t)(128 + k + 0) * SROW + i] = g.x;
        InT[(size_t)(128 + k + 1) * SROW + i] = g.y;
        InT[(size_t)(128 + k + 2) * SROW + i] = g.z;
        InT[(size_t)(128 + k + 3) * SROW + i] = g.w;
    }
    __syncthreads();

    mlp_tile(InT, WS, W1, b1, W2, b2, eout, r0, nvalid);
}

__global__ void __launch_bounds__(THREADS, 1) node_kernel(
    const float* __restrict__ x,
    const float* __restrict__ W1, const float* __restrict__ b1,
    const float* __restrict__ W2, const float* __restrict__ b2,
    float* __restrict__ xout, int N)
{
    extern __shared__ float sm[];
    float* InT = sm;
    float* WS  = sm + 256 * SROW;

    const int tid = threadIdx.x;
    const int r0 = blockIdx.x * BM;
    const int nvalid = min(BM, N - r0);

    const float4* x4 = (const float4*)x;
    const float4* ag4 = (const float4*)g_agg;
#pragma unroll
    for (int t = 0; t < (BM * 32) / THREADS; t++) {
        int idx = tid + t * THREADS;
        int i = idx >> 5, c4 = idx & 31;
        int k = c4 * 4;
        float4 v = make_float4(0.f, 0.f, 0.f, 0.f);
        float4 g = make_float4(0.f, 0.f, 0.f, 0.f);
        if (i < nvalid) {
            v = x4[(size_t)(r0 + i) * 32 + c4];
            g = ag4[(size_t)(r0 + i) * 32 + c4];
        }
        InT[(size_t)(k + 0) * SROW + i] = v.x;
        InT[(size_t)(k + 1) * SROW + i] = v.y;
        InT[(size_t)(k + 2) * SROW + i] = v.z;
        InT[(size_t)(k + 3) * SROW + i] = v.w;
        InT[(size_t)(128 + k + 0) * SROW + i] = g.x;
        InT[(size_t)(128 + k + 1) * SROW + i] = g.y;
        InT[(size_t)(128 + k + 2) * SROW + i] = g.z;
        InT[(size_t)(128 + k + 3) * SROW + i] = g.w;
    }
    __syncthreads();

    mlp_tile(InT, WS, W1, b1, W2, b2, xout, r0, nvalid);
}

extern "C" void kernel_launch(void* const* d_in, const int* in_sizes, int n_in,
                              void* d_out, int out_size)
{
    const float* x    = (const float*)d_in[0];
    const float* ea   = (const float*)d_in[1];
    const int*   eidx = (const int*)d_in[2];
    const float* eW1  = (const float*)d_in[3];
    const float* eb1  = (const float*)d_in[4];
    const float* eW2  = (const float*)d_in[5];
    const float* eb2  = (const float*)d_in[6];
    const float* nW1  = (const float*)d_in[7];
    const float* nb1  = (const float*)d_in[8];
    const float* nW2  = (const float*)d_in[9];
    const float* nb2  = (const float*)d_in[10];
    float* out = (float*)d_out;

    const int N = in_sizes[0] / DIM;
    const int E = in_sizes[1] / DIM;

    cudaFuncSetAttribute(edge_kernel, cudaFuncAttributeMaxDynamicSharedMemorySize, SMEM_BYTES);
    cudaFuncSetAttribute(node_kernel, cudaFuncAttributeMaxDynamicSharedMemorySize, SMEM_BYTES);

    // 0) detect edge_index dtype (int32 vs int64)
    detect_idx_kernel<<<1, 256>>>(eidx);

    // 1) zero the aggregation scratch
    int n4 = N * (DIM / 4);
    zero_agg_kernel<<<(n4 + THREADS - 1) / THREADS, THREADS>>>(n4);

    // 2) edge MLP (writes e) + scatter-sum of edge_attr into g_agg
    float* e_out = out + (size_t)N * DIM;   // output tuple order: (x_out, e)
    edge_kernel<<<(E + BM - 1) / BM, THREADS, SMEM_BYTES>>>(
        x, ea, eidx, eW1, eb1, eW2, eb2, e_out, E);

    // 3) node MLP on [x, agg] (stream order guarantees agg is complete)
    node_kernel<<<(N + BM - 1) / BM, THREADS, SMEM_BYTES>>>(
        x, nW1, nb1, nW2, nb2, out, N);
}